// round 1
// baseline (speedup 1.0000x reference)
#include <cuda_runtime.h>
#include <math.h>

#define SSP 16129   // 127*127
#define HW  127
#define BB  4
#define CC  256
#define CQ  32
#define CA  64
#define IMG 256
#define IMGSZ 65536

// ---------------- scratch (device globals; no allocation) ----------------
__device__ float g_xd[BB*CC*SSP];    // downsampled x   [b][c][i][j]
__device__ float g_q [BB*SSP*CQ];    // q               [b][s][cq]
__device__ float g_k [BB*SSP*CQ];    // k               [b][s][cq]
__device__ float g_a [BB*SSP*CA];    // resized attn    [b][s][ca]
__device__ float g_v [BB*SSP*CC];    // v               [b][s][c]
__device__ float g_E [BB*SSP*254];   // energies -> S (in place)
__device__ float g_A [BB*SSP*254];   // a-energies
__device__ float g_oH[BB*CC*SSP];    // outH [b][c][i][j]
__device__ float g_oW[BB*CC*SSP];    // outW [b][c][i][j]

// ---------------- 1) depthwise 4x4 stride-2 conv ----------------
__global__ void conv_down_kernel(const float* __restrict__ x, const float* __restrict__ wd) {
    int idx = blockIdx.x * blockDim.x + threadIdx.x;
    if (idx >= BB*CC*SSP) return;
    int j  = idx % HW;
    int i  = (idx / HW) % HW;
    int bc = idx / SSP;
    int c  = bc % CC;
    const float* px = x + (size_t)bc * IMGSZ + (2*i) * IMG + 2*j;
    const float* w  = wd + c * 16;
    float s = 0.f;
    #pragma unroll
    for (int dy = 0; dy < 4; dy++) {
        #pragma unroll
        for (int dx = 0; dx < 4; dx++)
            s += px[dy*IMG + dx] * w[dy*4 + dx];
    }
    g_xd[idx] = s;
}

// ---------------- 2) projections: Y[b][s][o] = sum_c X[b][c][s]*W[o][c] + bias[o] ----------------
__global__ __launch_bounds__(256) void gemm_proj_kernel(const float* __restrict__ W,
                                                        const float* __restrict__ bias,
                                                        int O, int which) {
    __shared__ float Xs[16][64];
    __shared__ float Ws[16][64];
    float* Y = (which == 0) ? g_q : (which == 1) ? g_k : g_v;
    int s0 = blockIdx.x * 64, o0 = blockIdx.y * 64, b = blockIdx.z;
    int tid = threadIdx.x;
    int tx = tid & 15, ty = tid >> 4;
    float acc[4][4] = {};
    const float* Xb = g_xd + (size_t)b * CC * SSP;
    for (int k0 = 0; k0 < CC; k0 += 16) {
        #pragma unroll
        for (int i = 0; i < 4; i++) {
            int e = tid + i*256;
            int kk = e >> 6, ss = e & 63;
            int s = s0 + ss;
            Xs[kk][ss] = (s < SSP) ? Xb[(size_t)(k0+kk)*SSP + s] : 0.f;
        }
        #pragma unroll
        for (int i = 0; i < 4; i++) {
            int e = tid + i*256;
            int oo = e >> 4, kk = e & 15;
            int o = o0 + oo;
            Ws[kk][oo] = (o < O) ? W[o*CC + k0 + kk] : 0.f;
        }
        __syncthreads();
        #pragma unroll
        for (int kk = 0; kk < 16; kk++) {
            float4 xv = *(const float4*)&Xs[kk][tx*4];
            float4 wv = *(const float4*)&Ws[kk][ty*4];
            acc[0][0] += wv.x*xv.x; acc[0][1] += wv.x*xv.y; acc[0][2] += wv.x*xv.z; acc[0][3] += wv.x*xv.w;
            acc[1][0] += wv.y*xv.x; acc[1][1] += wv.y*xv.y; acc[1][2] += wv.y*xv.z; acc[1][3] += wv.y*xv.w;
            acc[2][0] += wv.z*xv.x; acc[2][1] += wv.z*xv.y; acc[2][2] += wv.z*xv.z; acc[2][3] += wv.z*xv.w;
            acc[3][0] += wv.w*xv.x; acc[3][1] += wv.w*xv.y; acc[3][2] += wv.w*xv.z; acc[3][3] += wv.w*xv.w;
        }
        __syncthreads();
    }
    int ob = o0 + ty*4;
    if (ob < O) {
        float4 bi = *(const float4*)&bias[ob];
        #pragma unroll
        for (int is = 0; is < 4; is++) {
            int s = s0 + tx*4 + is;
            if (s < SSP) {
                float4 r;
                r.x = acc[0][is] + bi.x;
                r.y = acc[1][is] + bi.y;
                r.z = acc[2][is] + bi.z;
                r.w = acc[3][is] + bi.w;
                *(float4*)&Y[((size_t)b*SSP + s)*O + ob] = r;
            }
        }
    }
}

// ---------------- 3) bilinear downsample of attention_map 256->127, write [b][s][ca] ----------------
__global__ void resize_a_kernel(const float* __restrict__ am) {
    int idx = blockIdx.x * blockDim.x + threadIdx.x;
    if (idx >= BB*CA*SSP) return;
    int j = idx % HW, i = (idx / HW) % HW;
    int bca = idx / SSP;                 // b*64 + ca
    int b = bca / CA, ca = bca % CA;
    const float sc = 255.f / 126.f;
    float yf = i * sc; int y0 = (int)yf; float wy = yf - y0; int y1 = min(y0+1, IMG-1);
    float xf = j * sc; int x0 = (int)xf; float wx = xf - x0; int x1 = min(x0+1, IMG-1);
    const float* P = am + (size_t)bca * IMGSZ;
    float v = (P[y0*IMG+x0]*(1.f-wx) + P[y0*IMG+x1]*wx) * (1.f-wy)
            + (P[y1*IMG+x0]*(1.f-wx) + P[y1*IMG+x1]*wx) * wy;
    g_a[((size_t)b*SSP + i*HW + j)*CA + ca] = v;
}

// ---------------- 4) energies ----------------
// MODEW=false (H): block (j,b). out[b][i][j][t]   = sum_c Q[b][i*127+j][c]*K[b][t*127+j][c]  (mask t==i)
// MODEW=true  (W): block (i,b). out[b][i][p][127+t] = sum_c Q[b][i*127+p][c]*K[b][i*127+t][c]
template<int CDIM, bool MODEW, bool MASK>
__global__ __launch_bounds__(128) void energy_kernel(int which) {
    const float* Q = which ? g_a : g_q;
    const float* K = which ? g_a : g_k;
    float* out = which ? g_A : g_E;
    __shared__ float Qs[HW * CDIM];
    int fix = blockIdx.x, b = blockIdx.y;
    int t = threadIdx.x;
    const float* Qb = Q + (size_t)b * SSP * CDIM;
    for (int idx = t; idx < HW * CDIM; idx += 128) {
        int p = idx / CDIM, c = idx % CDIM;
        int s = MODEW ? fix*HW + p : p*HW + fix;
        Qs[idx] = Qb[(size_t)s*CDIM + c];
    }
    __syncthreads();
    if (t >= HW) return;
    int ks = MODEW ? fix*HW + t : t*HW + fix;
    float4 kr[CDIM/4];
    const float4* Kp = (const float4*)(K + ((size_t)b*SSP + ks)*CDIM);
    #pragma unroll
    for (int q = 0; q < CDIM/4; q++) kr[q] = Kp[q];
    for (int p = 0; p < HW; p++) {
        const float4* Qp = (const float4*)&Qs[p*CDIM];
        float acc = 0.f;
        #pragma unroll
        for (int q = 0; q < CDIM/4; q++) {
            float4 a4 = Qp[q];
            acc += a4.x * kr[q].x;
            acc += a4.y * kr[q].y;
            acc += a4.z * kr[q].z;
            acc += a4.w * kr[q].w;
        }
        size_t row = MODEW ? ((size_t)(b*HW + fix)*HW + p)
                           : ((size_t)(b*HW + p)*HW + fix);
        float val = (MASK && !MODEW && t == p) ? -INFINITY : acc;
        out[row*254 + (MODEW ? HW : 0) + t] = val;
    }
}

// ---------------- 5) fused triple softmax (in place into g_E) ----------------
__device__ __forceinline__ float bred(float v, bool mx, float* red) {
    #pragma unroll
    for (int o = 16; o; o >>= 1) {
        float u = __shfl_xor_sync(0xffffffffu, v, o);
        v = mx ? fmaxf(v, u) : v + u;
    }
    int lane = threadIdx.x & 31, w = threadIdx.x >> 5;
    if (lane == 0) red[w] = v;
    __syncthreads();
    float r = red[lane & 7];
    #pragma unroll
    for (int o = 4; o; o >>= 1) {
        float u = __shfl_xor_sync(0xffffffffu, r, o);
        r = mx ? fmaxf(r, u) : r + u;
    }
    __syncthreads();
    return r;
}

__global__ __launch_bounds__(256) void softmax3_kernel() {
    __shared__ float red[8];
    size_t base = (size_t)blockIdx.x * 254;
    int t = threadIdx.x;
    bool act = t < 254;
    float e = act ? g_E[base + t] : -INFINITY;
    float a = act ? g_A[base + t] : -INFINITY;

    float m  = bred(e, true, red);
    float ee = act ? expf(e - m) : 0.f;
    float s  = bred(ee, false, red);
    float ce = ee / s;

    float m2 = bred(a, true, red);
    float aa = act ? expf(a - m2) : 0.f;
    float s2 = bred(aa, false, red);
    float caq = aa / s2;

    float p  = ce * caq;
    float m3 = bred(act ? p : -INFINITY, true, red);
    float pe = act ? expf(p - m3) : 0.f;
    float s3 = bred(pe, false, red);
    if (act) g_E[base + t] = pe / s3;
}

// ---------------- 6) out GEMMs ----------------
// MODEW=false: block (j,b): outH[b][c][i][j] = sum_l S[b][i][j][l]     * v[b][l*127+j][c]
// MODEW=true : block (i,b): outW[b][c][i][j] = sum_m S[b][i][j][127+m] * v[b][i*127+m][c]
template<bool MODEW>
__global__ __launch_bounds__(256) void out_gemm_kernel() {
    __shared__ float sT[HW * 36];      // [u][tt], padded
    int fix = blockIdx.x, b = blockIdx.y;
    int c = threadIdx.x;
    float* out = MODEW ? g_oW : g_oH;
    for (int t0 = 0; t0 < HW; t0 += 32) {
        int tcnt = min(32, HW - t0);
        for (int idx = threadIdx.x; idx < tcnt * HW; idx += 256) {
            int tt = idx / HW, u = idx % HW;
            size_t row = MODEW ? ((size_t)(b*HW + fix)*HW + (t0+tt))
                               : ((size_t)(b*HW + (t0+tt))*HW + fix);
            sT[u*36 + tt] = g_E[row*254 + (MODEW ? HW : 0) + u];
        }
        __syncthreads();
        float acc[32];
        #pragma unroll
        for (int q = 0; q < 32; q++) acc[q] = 0.f;
        for (int u = 0; u < HW; u++) {
            int s = MODEW ? fix*HW + u : u*HW + fix;
            float vv = g_v[((size_t)b*SSP + s)*CC + c];
            const float4* row4 = (const float4*)&sT[u*36];
            #pragma unroll
            for (int q = 0; q < 8; q++) {
                float4 w = row4[q];
                acc[q*4+0] += w.x * vv;
                acc[q*4+1] += w.y * vv;
                acc[q*4+2] += w.z * vv;
                acc[q*4+3] += w.w * vv;
            }
        }
        #pragma unroll
        for (int tt = 0; tt < 32; tt++) {
            if (tt < tcnt) {
                size_t oi = MODEW ? (((size_t)(b*CC + c)*HW + fix)*HW + (t0+tt))
                                  : (((size_t)(b*CC + c)*HW + (t0+tt))*HW + fix);
                out[oi] = acc[tt];
            }
        }
        __syncthreads();
    }
}

// ---------------- 7) bilinear upsample 127->256, residual ----------------
__global__ void final_kernel(const float* __restrict__ x, const float* __restrict__ gamma,
                             float* __restrict__ out) {
    int idx = blockIdx.x * 256 + threadIdx.x;   // exact grid, 4*256*256*256
    int xx = idx & 255;
    int yy = (idx >> 8) & 255;
    int bc = idx >> 16;
    const float sc = 126.f / 255.f;
    float yf = yy * sc; int y0 = (int)yf; float wy = yf - y0; int y1 = min(y0+1, HW-1);
    float xf = xx * sc; int x0 = (int)xf; float wx = xf - x0; int x1 = min(x0+1, HW-1);
    size_t bse = (size_t)bc * SSP;
    int a00 = y0*HW + x0, a01 = y0*HW + x1, a10 = y1*HW + x0, a11 = y1*HW + x1;
    float hv = (g_oH[bse+a00]*(1.f-wx) + g_oH[bse+a01]*wx) * (1.f-wy)
             + (g_oH[bse+a10]*(1.f-wx) + g_oH[bse+a11]*wx) * wy;
    float wv = (g_oW[bse+a00]*(1.f-wx) + g_oW[bse+a01]*wx) * (1.f-wy)
             + (g_oW[bse+a10]*(1.f-wx) + g_oW[bse+a11]*wx) * wy;
    out[idx] = gamma[0] * (hv + wv) + x[idx];
}

// ---------------- launch ----------------
extern "C" void kernel_launch(void* const* d_in, const int* in_sizes, int n_in,
                              void* d_out, int out_size) {
    (void)in_sizes; (void)n_in; (void)out_size;
    const float* x  = (const float*)d_in[0];
    const float* am = (const float*)d_in[1];
    const float* wd = (const float*)d_in[2];
    const float* wq = (const float*)d_in[3];
    const float* bq = (const float*)d_in[4];
    const float* wk = (const float*)d_in[5];
    const float* bk = (const float*)d_in[6];
    const float* wv = (const float*)d_in[7];
    const float* bv = (const float*)d_in[8];
    const float* gm = (const float*)d_in[9];
    float* out = (float*)d_out;

    conv_down_kernel<<<(BB*CC*SSP + 255)/256, 256>>>(x, wd);

    gemm_proj_kernel<<<dim3(253, 1, BB), 256>>>(wq, bq, CQ, 0);
    gemm_proj_kernel<<<dim3(253, 1, BB), 256>>>(wk, bk, CQ, 1);
    gemm_proj_kernel<<<dim3(253, 4, BB), 256>>>(wv, bv, CC, 2);

    resize_a_kernel<<<(BB*CA*SSP + 255)/256, 256>>>(am);

    energy_kernel<CQ, false, true ><<<dim3(HW, BB), 128>>>(0);  // eH (masked)
    energy_kernel<CQ, true,  false><<<dim3(HW, BB), 128>>>(0);  // eW
    energy_kernel<CA, false, true ><<<dim3(HW, BB), 128>>>(1);  // aH (masked)
    energy_kernel<CA, true,  false><<<dim3(HW, BB), 128>>>(1);  // aW

    softmax3_kernel<<<BB*SSP, 256>>>();

    out_gemm_kernel<false><<<dim3(HW, BB), 256>>>();
    out_gemm_kernel<true ><<<dim3(HW, BB), 256>>>();

    final_kernel<<<(BB*CC*IMGSZ)/256, 256>>>(x, gm, out);
}

// round 2
// speedup vs baseline: 1.3610x; 1.3610x over previous
#include <cuda_runtime.h>
#include <math.h>

#define SSP 16129   // 127*127
#define HW  127
#define BB  4
#define CC  256
#define IMG 256
#define IMGSZ 65536

// ---------------- scratch (device globals; no allocation) ----------------
__device__ float g_xd[BB*CC*SSP];          // downsampled x  [b][c][s]
__device__ float g_qk[BB*SSP*64];          // q(0..31) | k(32..63)  [b][s][64]
__device__ float g_a [BB*SSP*64];          // resized attn  [b][s][64]
__device__ float g_v [BB*SSP*CC];          // v  [b][s][256]
__device__ float g_E [(size_t)BB*SSP*256]; // energies -> S (padded rows of 256)
__device__ float g_A [(size_t)BB*SSP*256]; // a-energies
__device__ float g_oH[(size_t)BB*CC*HW*128]; // outH transposed [b][c][j][i(pad128)]
__device__ float g_oW[(size_t)BB*CC*HW*128]; // outW            [b][c][i][j(pad128)]

// ---------------- f32x2 helpers ----------------
__device__ __forceinline__ unsigned long long dup2(float x) {
    unsigned long long r;
    asm("mov.b64 %0, {%1, %1};" : "=l"(r) : "f"(x));
    return r;
}
__device__ __forceinline__ void fma2(unsigned long long& d, unsigned long long a, unsigned long long b) {
    asm("fma.rn.f32x2 %0, %1, %2, %0;" : "+l"(d) : "l"(a), "l"(b));
}
__device__ __forceinline__ float2 unpack2(unsigned long long v) {
    float2 r;
    asm("mov.b64 {%0, %1}, %2;" : "=f"(r.x), "=f"(r.y) : "l"(v));
    return r;
}

// 128-wide microkernel: As/Bs are [16][132] smem tiles (k-major)
__device__ __forceinline__ void micro128(const float* As, const float* Bs,
                                         unsigned long long acc[8][4], int tx, int ty) {
    #pragma unroll
    for (int kk = 0; kk < 16; kk++) {
        float4 x0 = *(const float4*)&As[kk*132 + tx*4];
        float4 x1 = *(const float4*)&As[kk*132 + 64 + tx*4];
        ulonglong2 w0 = *(const ulonglong2*)&Bs[kk*132 + ty*8];
        ulonglong2 w1 = *(const ulonglong2*)&Bs[kk*132 + ty*8 + 4];
        unsigned long long xs[8];
        xs[0]=dup2(x0.x); xs[1]=dup2(x0.y); xs[2]=dup2(x0.z); xs[3]=dup2(x0.w);
        xs[4]=dup2(x1.x); xs[5]=dup2(x1.y); xs[6]=dup2(x1.z); xs[7]=dup2(x1.w);
        #pragma unroll
        for (int m = 0; m < 8; m++) {
            fma2(acc[m][0], xs[m], w0.x);
            fma2(acc[m][1], xs[m], w0.y);
            fma2(acc[m][2], xs[m], w1.x);
            fma2(acc[m][3], xs[m], w1.y);
        }
    }
}

// 64-wide microkernel: Bs is [16][68]
__device__ __forceinline__ void micro64(const float* As, const float* Bs,
                                        unsigned long long acc[8][2], int tx, int ty) {
    #pragma unroll
    for (int kk = 0; kk < 16; kk++) {
        float4 x0 = *(const float4*)&As[kk*132 + tx*4];
        float4 x1 = *(const float4*)&As[kk*132 + 64 + tx*4];
        ulonglong2 w0 = *(const ulonglong2*)&Bs[kk*68 + ty*4];
        unsigned long long xs[8];
        xs[0]=dup2(x0.x); xs[1]=dup2(x0.y); xs[2]=dup2(x0.z); xs[3]=dup2(x0.w);
        xs[4]=dup2(x1.x); xs[5]=dup2(x1.y); xs[6]=dup2(x1.z); xs[7]=dup2(x1.w);
        #pragma unroll
        for (int m = 0; m < 8; m++) {
            fma2(acc[m][0], xs[m], w0.x);
            fma2(acc[m][1], xs[m], w0.y);
        }
    }
}

// ---------------- 1) depthwise 4x4 stride-2 conv ----------------
__global__ void conv_down_kernel(const float* __restrict__ x, const float* __restrict__ wd) {
    int idx = blockIdx.x * blockDim.x + threadIdx.x;
    if (idx >= BB*CC*SSP) return;
    int j  = idx % HW;
    int i  = (idx / HW) % HW;
    int bc = idx / SSP;
    int c  = bc % CC;
    const float* px = x + (size_t)bc * IMGSZ + (2*i) * IMG + 2*j;
    const float* w  = wd + c * 16;
    float s = 0.f;
    #pragma unroll
    for (int dy = 0; dy < 4; dy++) {
        #pragma unroll
        for (int dx = 0; dx < 4; dx++)
            s += px[dy*IMG + dx] * w[dy*4 + dx];
    }
    g_xd[idx] = s;
}

// ---------------- 2) V projection: g_v[b][s][o] = sum_c xd[b][c][s]*Wv[o][c] + bv[o] ----------------
__global__ __launch_bounds__(256) void proj_v_kernel(const float* __restrict__ W,
                                                     const float* __restrict__ bias) {
    __shared__ __align__(16) float As[16*132];
    __shared__ __align__(16) float Bs[16*132];
    int s0 = blockIdx.x * 128, n0 = blockIdx.y * 128, b = blockIdx.z;
    int tid = threadIdx.x, tx = tid & 15, ty = tid >> 4;
    unsigned long long acc[8][4] = {};
    const float* Xb = g_xd + (size_t)b * CC * SSP;
    for (int k0 = 0; k0 < 256; k0 += 16) {
        #pragma unroll
        for (int i = 0; i < 8; i++) {
            int e = tid + i*256;
            int kk = e >> 7, mm = e & 127;
            int s = s0 + mm;
            As[kk*132 + mm] = (s < SSP) ? Xb[(size_t)(k0+kk)*SSP + s] : 0.f;
        }
        #pragma unroll
        for (int i = 0; i < 8; i++) {
            int e = tid + i*256;
            int nn = e >> 4, kk = e & 15;
            Bs[kk*132 + nn] = W[(n0+nn)*256 + k0 + kk];
        }
        __syncthreads();
        micro128(As, Bs, acc, tx, ty);
        __syncthreads();
    }
    int nb = n0 + ty*8;
    float4 bi0 = *(const float4*)&bias[nb];
    float4 bi1 = *(const float4*)&bias[nb+4];
    #pragma unroll
    for (int mi = 0; mi < 8; mi++) {
        int s = s0 + ((mi < 4) ? tx*4 + mi : 64 + tx*4 + mi - 4);
        if (s >= SSP) continue;
        float2 p0 = unpack2(acc[mi][0]), p1 = unpack2(acc[mi][1]);
        float2 p2 = unpack2(acc[mi][2]), p3 = unpack2(acc[mi][3]);
        float* o = g_v + ((size_t)b*SSP + s)*256 + nb;
        *(float4*)o     = make_float4(p0.x+bi0.x, p0.y+bi0.y, p1.x+bi0.z, p1.y+bi0.w);
        *(float4*)(o+4) = make_float4(p2.x+bi1.x, p2.y+bi1.y, p3.x+bi1.z, p3.y+bi1.w);
    }
}

// ---------------- 3) fused Q|K projection into g_qk (stride 64) ----------------
__global__ __launch_bounds__(256) void proj_qk_kernel(const float* __restrict__ wq, const float* __restrict__ bq,
                                                      const float* __restrict__ wk, const float* __restrict__ bk) {
    __shared__ __align__(16) float As[16*132];
    __shared__ __align__(16) float Bs[16*68];
    int s0 = blockIdx.x * 128, b = blockIdx.y;
    int tid = threadIdx.x, tx = tid & 15, ty = tid >> 4;
    unsigned long long acc[8][2] = {};
    const float* Xb = g_xd + (size_t)b * CC * SSP;
    for (int k0 = 0; k0 < 256; k0 += 16) {
        #pragma unroll
        for (int i = 0; i < 8; i++) {
            int e = tid + i*256;
            int kk = e >> 7, mm = e & 127;
            int s = s0 + mm;
            As[kk*132 + mm] = (s < SSP) ? Xb[(size_t)(k0+kk)*SSP + s] : 0.f;
        }
        #pragma unroll
        for (int i = 0; i < 4; i++) {
            int e = tid + i*256;
            int nn = e >> 4, kk = e & 15;
            Bs[kk*68 + nn] = (nn < 32) ? wq[nn*256 + k0 + kk] : wk[(nn-32)*256 + k0 + kk];
        }
        __syncthreads();
        micro64(As, Bs, acc, tx, ty);
        __syncthreads();
    }
    int nb = ty*4;
    float bv[4];
    #pragma unroll
    for (int ni = 0; ni < 4; ni++) {
        int n = nb + ni;
        bv[ni] = (n < 32) ? bq[n] : bk[n-32];
    }
    #pragma unroll
    for (int mi = 0; mi < 8; mi++) {
        int s = s0 + ((mi < 4) ? tx*4 + mi : 64 + tx*4 + mi - 4);
        if (s >= SSP) continue;
        float2 p0 = unpack2(acc[mi][0]), p1 = unpack2(acc[mi][1]);
        float* o = g_qk + ((size_t)b*SSP + s)*64 + nb;
        *(float4*)o = make_float4(p0.x+bv[0], p0.y+bv[1], p1.x+bv[2], p1.y+bv[3]);
    }
}

// ---------------- 4) bilinear downsample of attention_map 256->127 into g_a [b][s][64] ----------------
__global__ __launch_bounds__(256) void resize_a_kernel(const float* __restrict__ am) {
    __shared__ float t[32][65];
    int b = blockIdx.z, i = blockIdx.y, j0 = blockIdx.x * 32;
    const float sc = 255.f / 126.f;
    float yf = i * sc; int y0 = (int)yf; float wy = yf - y0; int y1 = min(y0+1, IMG-1);
    #pragma unroll
    for (int it = 0; it < 8; it++) {
        int e = threadIdx.x + it*256;
        int ca = e >> 5, jj = e & 31;
        int j = j0 + jj;
        if (j < HW) {
            float xf = j * sc; int x0 = (int)xf; float wx = xf - x0; int x1 = min(x0+1, IMG-1);
            const float* P = am + ((size_t)(b*64 + ca)) * IMGSZ;
            float v = (P[y0*IMG+x0]*(1.f-wx) + P[y0*IMG+x1]*wx) * (1.f-wy)
                    + (P[y1*IMG+x0]*(1.f-wx) + P[y1*IMG+x1]*wx) * wy;
            t[jj][ca] = v;
        }
    }
    __syncthreads();
    #pragma unroll
    for (int it = 0; it < 8; it++) {
        int e = threadIdx.x + it*256;
        int jj = e >> 6, ca = e & 63;
        int j = j0 + jj;
        if (j < HW)
            g_a[((size_t)b*SSP + i*HW + j)*64 + ca] = t[jj][ca];
    }
}

// ---------------- 5) energy GEMMs ----------------
// KDIM=32 -> SRC=g_qk (qoff=0, koff=32) -> OUT=g_E ; KDIM=64 -> SRC=g_a -> OUT=g_A
// MODEW=false (H): m=i, n=t, spatial = idx*127 + fix, diag mask, row offset 0
// MODEW=true  (W): m=p, n=t, spatial = fix*127 + idx, row offset 128
template<int KDIM, bool MODEW, bool MASK>
__global__ __launch_bounds__(256) void energy_kernel() {
    __shared__ __align__(16) float As[16*132];
    __shared__ __align__(16) float Bs[16*132];
    const float* SRC = (KDIM == 32) ? g_qk : g_a;
    float* OUT       = (KDIM == 32) ? g_E  : g_A;
    const int qoff = 0, koff = (KDIM == 32) ? 32 : 0;
    int fix = blockIdx.x, b = blockIdx.y;
    int tid = threadIdx.x, tx = tid & 15, ty = tid >> 4;
    unsigned long long acc[8][4] = {};
    const float* S = SRC + (size_t)b * SSP * 64;
    #pragma unroll
    for (int k0 = 0; k0 < KDIM; k0 += 16) {
        #pragma unroll
        for (int i = 0; i < 8; i++) {
            int e = tid + i*256;
            int mm = e >> 4, kk = e & 15;
            int sp = MODEW ? fix*HW + mm : mm*HW + fix;
            float qa = 0.f, kb = 0.f;
            if (mm < HW) {
                qa = S[(size_t)sp*64 + qoff + k0 + kk];
                kb = S[(size_t)sp*64 + koff + k0 + kk];
            }
            As[kk*132 + mm] = qa;
            Bs[kk*132 + mm] = kb;
        }
        __syncthreads();
        micro128(As, Bs, acc, tx, ty);
        __syncthreads();
    }
    const int noff = MODEW ? 128 : 0;
    #pragma unroll
    for (int mi = 0; mi < 8; mi++) {
        int m = (mi < 4) ? tx*4 + mi : 64 + tx*4 + mi - 4;
        if (m >= HW) continue;
        size_t row = MODEW ? ((size_t)(b*HW + fix)*HW + m) : ((size_t)(b*HW + m)*HW + fix);
        float v[8];
        #pragma unroll
        for (int np = 0; np < 4; np++) {
            float2 p = unpack2(acc[mi][np]);
            v[np*2] = p.x; v[np*2+1] = p.y;
        }
        #pragma unroll
        for (int ni = 0; ni < 8; ni++) {
            int n = ty*8 + ni;
            if (n == HW) v[ni] = -INFINITY;            // pad slot
            if (MASK && n == m) v[ni] = -INFINITY;     // diag mask (H)
        }
        float* o = OUT + row*256 + noff + ty*8;
        *(float4*)o     = make_float4(v[0], v[1], v[2], v[3]);
        *(float4*)(o+4) = make_float4(v[4], v[5], v[6], v[7]);
    }
}

// ---------------- 6) fused triple softmax, warp per row ----------------
__device__ __forceinline__ float wmax(float v) {
    #pragma unroll
    for (int o = 16; o; o >>= 1) v = fmaxf(v, __shfl_xor_sync(0xffffffffu, v, o));
    return v;
}
__device__ __forceinline__ float wsum(float v) {
    #pragma unroll
    for (int o = 16; o; o >>= 1) v += __shfl_xor_sync(0xffffffffu, v, o);
    return v;
}

__global__ __launch_bounds__(256) void softmax3_kernel() {
    int w = threadIdx.x >> 5, lane = threadIdx.x & 31;
    size_t row = (size_t)blockIdx.x * 8 + w;
    if (row >= (size_t)BB*SSP) return;
    float* Er = g_E + row*256;
    const float* Ar = g_A + row*256;
    float4 e0 = ((const float4*)Er)[lane];
    float4 e1 = ((const float4*)Er)[32 + lane];
    float4 a0 = ((const float4*)Ar)[lane];
    float4 a1 = ((const float4*)Ar)[32 + lane];
    float ev[8] = {e0.x,e0.y,e0.z,e0.w,e1.x,e1.y,e1.z,e1.w};
    float av[8] = {a0.x,a0.y,a0.z,a0.w,a1.x,a1.y,a1.z,a1.w};

    float m1 = -INFINITY, m2 = -INFINITY;
    #pragma unroll
    for (int i = 0; i < 8; i++) { m1 = fmaxf(m1, ev[i]); m2 = fmaxf(m2, av[i]); }
    m1 = wmax(m1); m2 = wmax(m2);
    float ce[8], ca[8], s1 = 0.f, s2 = 0.f;
    #pragma unroll
    for (int i = 0; i < 8; i++) {
        ce[i] = __expf(ev[i] - m1); s1 += ce[i];
        ca[i] = __expf(av[i] - m2); s2 += ca[i];
    }
    s1 = wsum(s1); s2 = wsum(s2);
    float r12 = 1.f / (s1 * s2);

    float pv[8];
    #pragma unroll
    for (int i = 0; i < 8; i++) pv[i] = ce[i] * ca[i] * r12;
    if (lane == 31) { pv[3] = -INFINITY; pv[7] = -INFINITY; }   // pad slots 127, 255

    float m3 = -INFINITY;
    #pragma unroll
    for (int i = 0; i < 8; i++) m3 = fmaxf(m3, pv[i]);
    m3 = wmax(m3);
    float s3 = 0.f, ov[8];
    #pragma unroll
    for (int i = 0; i < 8; i++) { ov[i] = __expf(pv[i] - m3); s3 += ov[i]; }
    s3 = wsum(s3);
    float r3 = 1.f / s3;
    ((float4*)Er)[lane]      = make_float4(ov[0]*r3, ov[1]*r3, ov[2]*r3, ov[3]*r3);
    ((float4*)Er)[32 + lane] = make_float4(ov[4]*r3, ov[5]*r3, ov[6]*r3, ov[7]*r3);
}

// ---------------- 7) out GEMMs ----------------
// MODEW=false (H): per (b,j): C[c][i] = sum_l S[b,i,j,l] * v[b, l*127+j, c] -> g_oH [b][c][j][i(128)]
// MODEW=true  (W): per (b,i): C[c][j] = sum_m S[b,i,j,128+m] * v[b, i*127+m, c] -> g_oW [b][c][i][j(128)]
template<bool MODEW>
__global__ __launch_bounds__(256) void outgemm_kernel() {
    __shared__ __align__(16) float As[16*132];
    __shared__ __align__(16) float Bs[16*132];
    int fix = blockIdx.x, c0 = blockIdx.y * 128, b = blockIdx.z;
    int tid = threadIdx.x, tx = tid & 15, ty = tid >> 4;
    unsigned long long acc[8][4] = {};
    const int noff = MODEW ? 128 : 0;
    for (int k0 = 0; k0 < HW; k0 += 16) {
        #pragma unroll
        for (int i = 0; i < 8; i++) {
            int e = tid + i*256;
            {   // A: v chunk (k-major, contiguous c)
                int kk = e >> 7, mm = e & 127;
                int k = k0 + kk;
                int sp = MODEW ? fix*HW + k : k*HW + fix;
                As[kk*132 + mm] = (k < HW) ? g_v[((size_t)b*SSP + sp)*256 + c0 + mm] : 0.f;
            }
            {   // B: S chunk (transpose load)
                int nn = e >> 4, kk = e & 15;
                int k = k0 + kk;
                size_t srow = MODEW ? ((size_t)(b*HW + fix)*HW + nn) : ((size_t)(b*HW + nn)*HW + fix);
                Bs[kk*132 + nn] = (nn < HW && k < HW) ? g_E[srow*256 + noff + k] : 0.f;
            }
        }
        __syncthreads();
        micro128(As, Bs, acc, tx, ty);
        __syncthreads();
    }
    float* O = MODEW ? g_oW : g_oH;
    #pragma unroll
    for (int mi = 0; mi < 8; mi++) {
        int c = c0 + ((mi < 4) ? tx*4 + mi : 64 + tx*4 + mi - 4);
        float2 p0 = unpack2(acc[mi][0]), p1 = unpack2(acc[mi][1]);
        float2 p2 = unpack2(acc[mi][2]), p3 = unpack2(acc[mi][3]);
        float* o = O + ((size_t)(b*256 + c)*HW + fix)*128 + ty*8;
        *(float4*)o     = make_float4(p0.x, p0.y, p1.x, p1.y);
        *(float4*)(o+4) = make_float4(p2.x, p2.y, p3.x, p3.y);
    }
}

// ---------------- 8) bilinear upsample 127->256, residual (2D tiled) ----------------
__global__ __launch_bounds__(256) void final_kernel(const float* __restrict__ x,
                                                    const float* __restrict__ gamma,
                                                    float* __restrict__ out) {
    int bc = blockIdx.z;
    int xx = blockIdx.x * 32 + (threadIdx.x & 31);
    int yy = blockIdx.y * 8  + (threadIdx.x >> 5);
    const float sc = 126.f / 255.f;
    float yf = yy * sc; int y0 = (int)yf; float wy = yf - y0; int y1 = min(y0+1, HW-1);
    float xf = xx * sc; int x0 = (int)xf; float wx = xf - x0; int x1 = min(x0+1, HW-1);
    const float* Ht = g_oH + (size_t)bc * HW * 128;   // [j][i]
    const float* Wt = g_oW + (size_t)bc * HW * 128;   // [i][j]
    float h00 = Ht[x0*128 + y0], h01 = Ht[x0*128 + y1];
    float h10 = Ht[x1*128 + y0], h11 = Ht[x1*128 + y1];
    float hv = (h00*(1.f-wy) + h01*wy)*(1.f-wx) + (h10*(1.f-wy) + h11*wy)*wx;
    float w00 = Wt[y0*128 + x0], w01 = Wt[y0*128 + x1];
    float w10 = Wt[y1*128 + x0], w11 = Wt[y1*128 + x1];
    float wv = (w00*(1.f-wx) + w01*wx)*(1.f-wy) + (w10*(1.f-wx) + w11*wx)*wy;
    size_t idx = (size_t)bc * IMGSZ + yy*IMG + xx;
    out[idx] = gamma[0] * (hv + wv) + x[idx];
}

// ---------------- launch ----------------
extern "C" void kernel_launch(void* const* d_in, const int* in_sizes, int n_in,
                              void* d_out, int out_size) {
    (void)in_sizes; (void)n_in; (void)out_size;
    const float* x  = (const float*)d_in[0];
    const float* am = (const float*)d_in[1];
    const float* wd = (const float*)d_in[2];
    const float* wq = (const float*)d_in[3];
    const float* bq = (const float*)d_in[4];
    const float* wk = (const float*)d_in[5];
    const float* bk = (const float*)d_in[6];
    const float* wv = (const float*)d_in[7];
    const float* bv = (const float*)d_in[8];
    const float* gm = (const float*)d_in[9];
    float* out = (float*)d_out;

    conv_down_kernel<<<(BB*CC*SSP + 255)/256, 256>>>(x, wd);
    resize_a_kernel<<<dim3(4, HW, BB), 256>>>(am);

    proj_qk_kernel<<<dim3(127, BB), 256>>>(wq, bq, wk, bk);
    proj_v_kernel<<<dim3(127, 2, BB), 256>>>(wv, bv);

    energy_kernel<32, false, true ><<<dim3(HW, BB), 256>>>();  // eH (masked)
    energy_kernel<32, true,  false><<<dim3(HW, BB), 256>>>();  // eW
    energy_kernel<64, false, true ><<<dim3(HW, BB), 256>>>();  // aH (masked)
    energy_kernel<64, true,  false><<<dim3(HW, BB), 256>>>();  // aW

    softmax3_kernel<<<(BB*SSP + 7)/8, 256>>>();

    outgemm_kernel<false><<<dim3(HW, 2, BB), 256>>>();
    outgemm_kernel<true ><<<dim3(HW, 2, BB), 256>>>();

    final_kernel<<<dim3(8, 32, BB*CC), 256>>>(x, gm, out);
}